// round 13
// baseline (speedup 1.0000x reference)
#include <cuda_runtime.h>
#include <cstdint>
#include <cfloat>

#define NH    218
#define NHP   224        // padded h stride (16B-aligned rows)
#define NSUB  47524      // 218*218
#define NROWS 64         // B * C_OUT * C_IN
#define QG    55         // quad-groups per h1 row (55*4 = 220 >= 218)
#define TPB   220        // 4 h1 rows * 55 quad-groups

typedef unsigned long long ull;

// ---------------- device globals (no allocations allowed) ----------------
__device__ __align__(16) float g_Wn[32 * 24 * 16];          // -2*Kstruct, [oi][p][c]
__device__ float g_c2[32];                                   // ||K||^2+||R||^2+||C||^2
__device__ __align__(16) float g_rpn[2 * 32 * 24 * NHP];     // rpart [b][oi][p][h1]
__device__ __align__(16) float g_cpn[2 * 32 * 24 * NHP];     // cpart [b][oi][p][h2]
__device__ float g_pmax[NROWS][NH];
__device__ float g_psum[NROWS][NH];
__device__ float g_fac[NROWS][NH];
__device__ __align__(16) float g_sims[(size_t)NROWS * NSUB]; // m, then exp(m - blkmax)

__constant__ unsigned char c_P[24][4] = {
  {0,1,2,3},{0,1,3,2},{0,2,1,3},{0,2,3,1},{0,3,1,2},{0,3,2,1},
  {1,0,2,3},{1,0,3,2},{1,2,0,3},{1,2,3,0},{1,3,0,2},{1,3,2,0},
  {2,0,1,3},{2,0,3,1},{2,1,0,3},{2,1,3,0},{2,3,0,1},{2,3,1,0},
  {3,0,1,2},{3,0,2,1},{3,1,0,2},{3,1,2,0},{3,2,0,1},{3,2,1,0}
};

// ---------------- packed f32x2 helpers -----------------------------------
__device__ __forceinline__ ull dup2(float f) {
    ull r;
    asm("mov.b64 %0, {%1, %1};" : "=l"(r) : "f"(f));
    return r;
}
__device__ __forceinline__ ull pk2(float a, float b) {
    ull r;
    asm("mov.b64 %0, {%1, %2};" : "=l"(r) : "f"(a), "f"(b));
    return r;
}
__device__ __forceinline__ ull add2(ull a, ull b) {
    ull r;
    asm("add.rn.f32x2 %0, %1, %2;" : "=l"(r) : "l"(a), "l"(b));
    return r;
}
#define FMA2(acc, x, w) asm("fma.rn.f32x2 %0, %1, %2, %0;" : "+l"(acc) : "l"(x), "l"(w))
#define UNPK(v, lo, hi) asm("mov.b64 {%0, %1}, %2;" : "=f"(lo), "=f"(hi) : "l"(v))

// ---------------- prep 1: weights + c2 ------------------------------------
__global__ void prep_w_kernel(const float* __restrict__ ks,
                              const float* __restrict__ kr,
                              const float* __restrict__ kc) {
    int tid = threadIdx.x;
    if (tid < 32) {
        int oi = tid; float s = 0.0f;
        const float* a = ks + oi * 16;
        #pragma unroll
        for (int j = 0; j < 16; j++) s += a[j] * a[j];
        const float* r = kr + oi * 4; const float* c = kc + oi * 4;
        #pragma unroll
        for (int j = 0; j < 4; j++) { s += r[j] * r[j]; s += c[j] * c[j]; }
        g_c2[oi] = s;
    }
    for (int e = tid; e < 32 * 24 * 16; e += blockDim.x) {
        int c = e & 15; int t2 = e >> 4;
        int p = t2 % 24; int oi = t2 / 24;
        int a = c >> 2, bb = c & 3;
        float val = ks[oi * 16 + (int)c_P[p][a] * 4 + (int)c_P[p][bb]];
        g_Wn[(oi * 24 + p) * 16 + c] = -2.0f * val;
    }
}

// ---------------- prep 2: rp/cp tables ------------------------------------
__global__ void prep_tab_kernel(const float* __restrict__ types,
                                const float* __restrict__ kr,
                                const float* __restrict__ kc) {
    int idx = blockIdx.x, tid = threadIdx.x;
    int b = idx / NH, h = idx - b * NH;
    for (int e = tid; e < 768; e += blockDim.x) {
        int oi = e / 24, p = e % 24;
        int i = oi & 3;
        const float* tp = types + (b * 4 + i) * 224 + h;
        float t0 = tp[0], t1 = tp[2], t2 = tp[4], t3 = tp[6];
        float t2s = t0 * t0 + t1 * t1 + t2 * t2 + t3 * t3;
        const float* krp = kr + oi * 4;
        const float* kcp = kc + oi * 4;
        float rd = t0 * krp[c_P[p][0]] + t1 * krp[c_P[p][1]] + t2 * krp[c_P[p][2]] + t3 * krp[c_P[p][3]];
        float cd = t0 * kcp[c_P[p][0]] + t1 * kcp[c_P[p][1]] + t2 * kcp[c_P[p][2]] + t3 * kcp[c_P[p][3]];
        size_t lin = ((size_t)(b * 32 + oi) * 24 + p) * NHP + h;
        g_rpn[lin] = t2s - 2.0f * rd;
        g_cpn[lin] = t2s - 2.0f * cd;
    }
}

// ---------------- prep 3: h_mean closed form -------------------------------
__global__ void prep_h_kernel(const float* __restrict__ feats, float* __restrict__ out) {
    int b = blockIdx.x, f = threadIdx.x;
    float acc = 0.0f;
    for (int n = 0; n < 224; n++) {
        int lo = (n >= NH) ? ((n - (NH - 2)) >> 1) : 0;
        int hi = min(3, n >> 1);
        acc += (float)(hi - lo + 1) * feats[(b * 224 + n) * 128 + f];
    }
    out[b * 128 + f] = acc * (2.0f / (float)NH);
}

// ---------------- sims: 4 subs/thread, 4 acc chains (both o per p) --------
// thread = (lh in 0..3, quad-group u in 0..54): subs h2 = 4u..4u+3
// h1 = 4*blockIdx.x + lh; h1 masking required (tiles span 220 > 218).
__global__ void __launch_bounds__(TPB, 3)
sims_kernel(const float* __restrict__ graph) {
    __shared__ __align__(16) ull sw2[8 * 24 * 16];   // 24 KB dup weights [oiL][p][c]
    __shared__ __align__(16) ull srpd[4][8][24];     // 6 KB dup (c2+rp) per h1
    __shared__ unsigned smaxu[4][8];
    __shared__ float    smaxf[4][8];
    __shared__ float    ssumv[4][8];

    int t  = threadIdx.x;
    int b  = blockIdx.y;
    int zo = blockIdx.z;              // o-pair: o = zo*2 + oL
    int h1base = blockIdx.x * 4;

    {
        const float* srcw = g_Wn + zo * 8 * 384;
        for (int e = t; e < 3072; e += TPB) sw2[e] = dup2(srcw[e]);
        for (int e = t; e < 768; e += TPB) {
            int lh = e / 192, r = e % 192, oiL = r / 24, p = r % 24;
            int h1s = min(h1base + lh, NH - 1);
            float v = g_c2[zo * 8 + oiL] +
                      g_rpn[((size_t)(b * 32 + zo * 8 + oiL) * 24 + p) * NHP + h1s];
            srpd[lh][oiL][p] = dup2(v);
        }
        if (t < 32) { smaxu[t >> 3][t & 7] = 0u; ssumv[t >> 3][t & 7] = 0.0f; }
    }
    __syncthreads();

    int lh = t / QG, u = t - lh * QG;
    int h1 = h1base + lh;
    bool h1v = h1 < NH;
    int h1c = h1v ? h1 : NH - 1;
    int h2b = 4 * u;
    int nk = h1v ? ((h2b + 4 <= NH) ? 4 : NH - h2b) : 0;  // 4, 2 (u=54), or 0
    bool fullq = (u < QG - 1);

    #pragma unroll 1
    for (int i = 0; i < 4; i++) {
        ull xq[4][5];
        float x20 = 0.f, x21 = 0.f, x22 = 0.f, x23 = 0.f;
        const float* gp = graph + (((size_t)(b * 4 + i) * 224) + h1c) * 224 + h2b;
        #pragma unroll
        for (int a = 0; a < 4; a++) {
            const float* ad = gp + (2 * a) * 224;
            float4 v0 = *(const float4*)ad;          // g0..g3
            float4 v1 = *(const float4*)(ad + 4);    // g4..g7
            float2 v2 = fullq ? *(const float2*)(ad + 8) : make_float2(0.f, 0.f);
            xq[a][0] = pk2(v0.x, v0.y);
            xq[a][1] = pk2(v0.z, v0.w);
            xq[a][2] = pk2(v1.x, v1.y);
            xq[a][3] = pk2(v1.z, v1.w);
            xq[a][4] = pk2(v2.x, v2.y);
            x20 = fmaf(v0.x, v0.x, fmaf(v0.z, v0.z, fmaf(v1.x, v1.x, fmaf(v1.z, v1.z, x20))));
            x21 = fmaf(v0.y, v0.y, fmaf(v0.w, v0.w, fmaf(v1.y, v1.y, fmaf(v1.w, v1.w, x21))));
            x22 = fmaf(v0.z, v0.z, fmaf(v1.x, v1.x, fmaf(v1.z, v1.z, fmaf(v2.x, v2.x, x22))));
            x23 = fmaf(v0.w, v0.w, fmaf(v1.y, v1.y, fmaf(v1.w, v1.w, fmaf(v2.y, v2.y, x23))));
        }
        ull b01 = pk2(x20, x21);
        ull b23 = pk2(x22, x23);

        // both o-channels in one p loop: 4 independent accumulator chains.
        // oiL block stride: 24p*16c = 384 ull = 192 ulonglong2.
        // oiL -> oiL+4:  weights +4*192 ulonglong2 = +768, rpd +4*24, cpg +4*24*NHP.
        const ulonglong2* wb0 = (const ulonglong2*)(sw2 + i * 384);        // oiL = i
        const ull* rpd0 = &srpd[lh][i][0];                                  // oiL = i
        const float* cpg0 = g_cpn + ((size_t)(b * 32 + zo * 8 + i) * 24) * NHP + h2b;
        float m0 = FLT_MAX, m1 = FLT_MAX, m2 = FLT_MAX, m3 = FLT_MAX;
        float n0 = FLT_MAX, n1 = FLT_MAX, n2 = FLT_MAX, n3 = FLT_MAX;
        #pragma unroll 2
        for (int p = 0; p < 24; p++) {
            ulonglong2 cpq0 = *(const ulonglong2*)(cpg0 + p * NHP);
            ulonglong2 cpq1 = *(const ulonglong2*)(cpg0 + 4 * 24 * NHP + p * NHP);
            ull crp0 = rpd0[p];
            ull crp1 = rpd0[4 * 24 + p];
            ull A0 = add2(add2(b01, crp0), cpq0.x);
            ull A1 = add2(add2(b23, crp0), cpq0.y);
            ull B0 = add2(add2(b01, crp1), cpq1.x);
            ull B1 = add2(add2(b23, crp1), cpq1.y);
            const ulonglong2* wp0 = wb0 + p * 8;
            #pragma unroll
            for (int j = 0; j < 8; j++) {             // c pair (2j, 2j+1)
                ulonglong2 w0 = wp0[j];               // LDS.128 broadcast, oiL=i
                ulonglong2 w1 = wp0[768 + j];         // oiL=4+i (FIXED: was 384)
                int a = j >> 1, bb = (2 * j) & 3;
                FMA2(A0, xq[a][bb],     w0.x);
                FMA2(A1, xq[a][bb + 1], w0.x);
                FMA2(B0, xq[a][bb],     w1.x);
                FMA2(B1, xq[a][bb + 1], w1.x);
                FMA2(A0, xq[a][bb + 1], w0.y);
                FMA2(A1, xq[a][bb + 2], w0.y);
                FMA2(B0, xq[a][bb + 1], w1.y);
                FMA2(B1, xq[a][bb + 2], w1.y);
            }
            float d0, d1, d2, d3, e0, e1, e2, e3;
            UNPK(A0, d0, d1); UNPK(A1, d2, d3);
            UNPK(B0, e0, e1); UNPK(B1, e2, e3);
            m0 = fminf(m0, d0); m1 = fminf(m1, d1);
            m2 = fminf(m2, d2); m3 = fminf(m3, d3);
            n0 = fminf(n0, e0); n1 = fminf(n1, e1);
            n2 = fminf(n2, e2); n3 = fminf(n3, e3);
        }
        if (nk) {
            #pragma unroll
            for (int oL = 0; oL < 2; oL++) {
                int oiL = oL * 4 + i;
                float q0 = oL ? n0 : m0, q1 = oL ? n1 : m1;
                float q2 = oL ? n2 : m2, q3 = oL ? n3 : m3;
                int row = b * 32 + zo * 8 + oiL;
                float* sp = g_sims + (size_t)row * NSUB + h1 * NH + h2b;
                *(float2*)sp = make_float2(q0, q1);
                float tm = fmaxf(q0, q1);
                if (nk == 4) {
                    *(float2*)(sp + 2) = make_float2(q2, q3);
                    tm = fmaxf(tm, fmaxf(q2, q3));
                }
                unsigned uu  = __float_as_uint(tm);
                unsigned key = (uu & 0x80000000u) ? ~uu : (uu | 0x80000000u);
                atomicMax(&smaxu[lh][oiL], key);
            }
        }
    }

    __syncthreads();
    if (t < 32) {
        unsigned uu = smaxu[t >> 3][t & 7];
        smaxf[t >> 3][t & 7] = (uu & 0x80000000u) ? __uint_as_float(uu & 0x7fffffffu)
                                                  : __uint_as_float(~uu);
    }
    __syncthreads();

    // phase 2: in-place exp (thread re-reads only its own writes)
    if (nk) {
        #pragma unroll 1
        for (int oiL = 0; oiL < 8; oiL++) {
            int row = b * 32 + zo * 8 + oiL;
            float mx = smaxf[lh][oiL];
            float* sp = g_sims + (size_t)row * NSUB + h1 * NH + h2b;
            float2 v01 = *(float2*)sp;
            float e0 = __expf(v01.x - mx), e1 = __expf(v01.y - mx);
            *(float2*)sp = make_float2(e0, e1);
            float ssv = e0 + e1;
            if (nk == 4) {
                float2 v23 = *(float2*)(sp + 2);
                float e2 = __expf(v23.x - mx), e3 = __expf(v23.y - mx);
                *(float2*)(sp + 2) = make_float2(e2, e3);
                ssv += e2 + e3;
            }
            atomicAdd(&ssumv[lh][oiL], ssv);
        }
    }
    __syncthreads();
    if (t < 32) {
        int lh2 = t >> 3, oiL = t & 7, h1w = h1base + lh2;
        if (h1w < NH) {
            int row = b * 32 + zo * 8 + oiL;
            g_pmax[row][h1w] = smaxf[lh2][oiL];
            g_psum[row][h1w] = ssumv[lh2][oiL];
        }
    }
}

// ---------------- combine: global max/sum + factor table -------------------
__global__ void combine_kernel() {
    __shared__ float red[256];
    int row = blockIdx.x, tid = threadIdx.x;
    float pm = (tid < NH) ? g_pmax[row][tid] : -FLT_MAX;
    red[tid] = pm; __syncthreads();
    #pragma unroll
    for (int st = 128; st; st >>= 1) {
        if (tid < st) red[tid] = fmaxf(red[tid], red[tid + st]);
        __syncthreads();
    }
    float gmx = red[0];
    __syncthreads();
    float ex = (tid < NH) ? __expf(pm - gmx) : 0.0f;
    red[tid] = (tid < NH) ? g_psum[row][tid] * ex : 0.0f;
    __syncthreads();
    #pragma unroll
    for (int st = 128; st; st >>= 1) {
        if (tid < st) red[tid] += red[tid + st];
        __syncthreads();
    }
    float S = red[0];
    if (tid < NH) g_fac[row][tid] = ex / S;
}

// ---------------- writeout: grid-stride float4 streaming -------------------
__global__ void writeout_kernel(float* __restrict__ out) {
    int row = blockIdx.y;
    const float* fr = g_fac[row];
    const float* sp = g_sims + (size_t)row * NSUB;
    float* op = out + 256 + (size_t)row * NSUB;
    int idx = (blockIdx.x * 1024 + threadIdx.x) * 4;
    if (idx + 4 <= NSUB) {
        float4 e = *(const float4*)(sp + idx);
        int h1a = idx / NH, h1b = (idx + 1) / NH, h1c = (idx + 2) / NH, h1d = (idx + 3) / NH;
        float4 r;
        r.x = (1.0f - e.x * fr[h1a]) * (1.0f / (float)NSUB);
        r.y = (1.0f - e.y * fr[h1b]) * (1.0f / (float)NSUB);
        r.z = (1.0f - e.z * fr[h1c]) * (1.0f / (float)NSUB);
        r.w = (1.0f - e.w * fr[h1d]) * (1.0f / (float)NSUB);
        *(float4*)(op + idx) = r;
    } else {
        for (int j = idx; j < NSUB; j++)
            op[j] = (1.0f - sp[j] * fr[j / NH]) * (1.0f / (float)NSUB);
    }
}

// ---------------- launch ---------------------------------------------------
extern "C" void kernel_launch(void* const* d_in, const int* in_sizes, int n_in,
                              void* d_out, int out_size) {
    const float* graph    = (const float*)d_in[0];
    const float* types    = (const float*)d_in[1];
    const float* features = (const float*)d_in[2];
    const float* ks       = (const float*)d_in[3];
    const float* kr       = (const float*)d_in[4];
    const float* kc       = (const float*)d_in[5];
    float* out = (float*)d_out;

    prep_w_kernel<<<1, 256>>>(ks, kr, kc);
    prep_tab_kernel<<<2 * NH, 256>>>(types, kr, kc);
    prep_h_kernel<<<2, 128>>>(features, out);
    sims_kernel<<<dim3(QG, 2, 4), TPB>>>(graph);      // launch #4 -> ncu capture
    combine_kernel<<<NROWS, 256>>>();
    writeout_kernel<<<dim3((NSUB + 4095) / 4096, NROWS), 1024>>>(out);
}

// round 15
// speedup vs baseline: 1.2310x; 1.2310x over previous
#include <cuda_runtime.h>
#include <cstdint>
#include <cfloat>

#define NH    218
#define NHP   224        // padded h stride (16B-aligned rows)
#define NSUB  47524      // 218*218
#define NROWS 64         // B * C_OUT * C_IN
#define QG    55         // quad-groups per h1 row (55*4 = 220 >= 218)
#define TPB   220        // 4 h1 rows * 55 quad-groups

typedef unsigned long long ull;

// ---------------- device globals (no allocations allowed) ----------------
__device__ __align__(16) float g_Wn[32 * 24 * 16];          // -2*Kstruct, [oi][p][c]
__device__ float g_c2[32];                                   // ||K||^2+||R||^2+||C||^2
__device__ __align__(16) float g_rpn[2 * 32 * 24 * NHP];     // rpart [b][oi][p][h1]
__device__ __align__(16) float g_cpn[2 * 32 * 24 * NHP];     // cpart [b][oi][p][h2]
__device__ float g_pmax[NROWS][NH];
__device__ float g_psum[NROWS][NH];
__device__ float g_fac[NROWS][NH];
__device__ __align__(16) float g_sims[(size_t)NROWS * NSUB]; // m, then exp(m - blkmax)

__constant__ unsigned char c_P[24][4] = {
  {0,1,2,3},{0,1,3,2},{0,2,1,3},{0,2,3,1},{0,3,1,2},{0,3,2,1},
  {1,0,2,3},{1,0,3,2},{1,2,0,3},{1,2,3,0},{1,3,0,2},{1,3,2,0},
  {2,0,1,3},{2,0,3,1},{2,1,0,3},{2,1,3,0},{2,3,0,1},{2,3,1,0},
  {3,0,1,2},{3,0,2,1},{3,1,0,2},{3,1,2,0},{3,2,0,1},{3,2,1,0}
};

// ---------------- packed f32x2 helpers -----------------------------------
__device__ __forceinline__ ull dup2(float f) {
    ull r;
    asm("mov.b64 %0, {%1, %1};" : "=l"(r) : "f"(f));
    return r;
}
__device__ __forceinline__ ull pk2(float a, float b) {
    ull r;
    asm("mov.b64 %0, {%1, %2};" : "=l"(r) : "f"(a), "f"(b));
    return r;
}
__device__ __forceinline__ ull add2(ull a, ull b) {
    ull r;
    asm("add.rn.f32x2 %0, %1, %2;" : "=l"(r) : "l"(a), "l"(b));
    return r;
}
#define FMA2(acc, x, w) asm("fma.rn.f32x2 %0, %1, %2, %0;" : "+l"(acc) : "l"(x), "l"(w))
#define UNPK(v, lo, hi) asm("mov.b64 {%0, %1}, %2;" : "=f"(lo), "=f"(hi) : "l"(v))

// ---------------- fused prep: weights+c2 / h_mean / rp-cp tables ----------
__global__ void prep_all_kernel(const float* __restrict__ types,
                                const float* __restrict__ feats,
                                const float* __restrict__ ks,
                                const float* __restrict__ kr,
                                const float* __restrict__ kc,
                                float* __restrict__ out) {
    int bid = blockIdx.x, tid = threadIdx.x;
    if (bid == 0) {
        if (tid < 32) {
            int oi = tid; float s = 0.0f;
            const float* a = ks + oi * 16;
            #pragma unroll
            for (int j = 0; j < 16; j++) s += a[j] * a[j];
            const float* r = kr + oi * 4; const float* c = kc + oi * 4;
            #pragma unroll
            for (int j = 0; j < 4; j++) { s += r[j] * r[j]; s += c[j] * c[j]; }
            g_c2[oi] = s;
        }
        for (int e = tid; e < 32 * 24 * 16; e += blockDim.x) {
            int c = e & 15; int t2 = e >> 4;
            int p = t2 % 24; int oi = t2 / 24;
            int a = c >> 2, bb = c & 3;
            float val = ks[oi * 16 + (int)c_P[p][a] * 4 + (int)c_P[p][bb]];
            g_Wn[(oi * 24 + p) * 16 + c] = -2.0f * val;
        }
    } else if (bid <= 2) {
        int b = bid - 1;
        if (tid < 128) {
            float acc = 0.0f;
            for (int n = 0; n < 224; n++) {
                int lo = (n >= NH) ? ((n - (NH - 2)) >> 1) : 0;
                int hi = min(3, n >> 1);
                acc += (float)(hi - lo + 1) * feats[(b * 224 + n) * 128 + tid];
            }
            out[b * 128 + tid] = acc * (2.0f / (float)NH);
        }
    } else {
        int idx = bid - 3;
        int b = idx / NH, h = idx - b * NH;
        for (int e = tid; e < 768; e += blockDim.x) {
            int oi = e / 24, p = e % 24;
            int i = oi & 3;
            const float* tp = types + (b * 4 + i) * 224 + h;
            float t0 = tp[0], t1 = tp[2], t2 = tp[4], t3 = tp[6];
            float t2s = t0 * t0 + t1 * t1 + t2 * t2 + t3 * t3;
            const float* krp = kr + oi * 4;
            const float* kcp = kc + oi * 4;
            float rd = t0 * krp[c_P[p][0]] + t1 * krp[c_P[p][1]] + t2 * krp[c_P[p][2]] + t3 * krp[c_P[p][3]];
            float cd = t0 * kcp[c_P[p][0]] + t1 * kcp[c_P[p][1]] + t2 * kcp[c_P[p][2]] + t3 * kcp[c_P[p][3]];
            size_t lin = ((size_t)(b * 32 + oi) * 24 + p) * NHP + h;
            g_rpn[lin] = t2s - 2.0f * rd;
            g_cpn[lin] = t2s - 2.0f * cd;
        }
    }
}

// ---------------- sims: R7-exact 4-subs/thread FFMA2 kernel ----------------
// thread = (lh in 0..3, quad-group u in 0..54): subs h2 = 4u..4u+3
// h1 = 4*blockIdx.x + lh; h1 masking required (tiles span 220 > 218).
__global__ void __launch_bounds__(TPB, 3)
sims_kernel(const float* __restrict__ graph) {
    __shared__ __align__(16) float sw[8 * 24 * 16];   // 12 KB: [oiL][p][c]
    __shared__ float    srp[4][8][24];                // rpart for 4 h1
    __shared__ float    sc2s[8];
    __shared__ unsigned smaxu[4][8];
    __shared__ float    smaxf[4][8];
    __shared__ float    ssumv[4][8];

    int t  = threadIdx.x;
    int b  = blockIdx.y;
    int zo = blockIdx.z;              // o-pair index: o = zo*2 + oL
    int h1base = blockIdx.x * 4;

    {
        const float4* srcw = (const float4*)(g_Wn + zo * 8 * 384);
        float4* dstw = (float4*)sw;
        for (int e = t; e < 768; e += TPB) dstw[e] = srcw[e];
        for (int e = t; e < 768; e += TPB) {
            int lh = e / 192, r = e % 192, oiL = r / 24, p = r % 24;
            int h1s = min(h1base + lh, NH - 1);
            srp[lh][oiL][p] = g_rpn[((size_t)(b * 32 + zo * 8 + oiL) * 24 + p) * NHP + h1s];
        }
        if (t < 8) sc2s[t] = g_c2[zo * 8 + t];
        if (t < 32) { smaxu[t >> 3][t & 7] = 0u; ssumv[t >> 3][t & 7] = 0.0f; }
    }
    __syncthreads();

    int lh = t / QG, u = t - lh * QG;
    int h1 = h1base + lh;
    bool h1v = h1 < NH;
    int h1c = h1v ? h1 : NH - 1;
    int h2b = 4 * u;
    int nk = h1v ? ((h2b + 4 <= NH) ? 4 : NH - h2b) : 0;  // 4, 2 (u=54), or 0
    bool fullq = (u < QG - 1);

    #pragma unroll 1
    for (int i = 0; i < 4; i++) {
        ull xq[4][5];
        float x20 = 0.f, x21 = 0.f, x22 = 0.f, x23 = 0.f;
        const float* gp = graph + (((size_t)(b * 4 + i) * 224) + h1c) * 224 + h2b;
        #pragma unroll
        for (int a = 0; a < 4; a++) {
            const float* ad = gp + (2 * a) * 224;
            float4 v0 = *(const float4*)ad;          // g0..g3
            float4 v1 = *(const float4*)(ad + 4);    // g4..g7
            float2 v2 = fullq ? *(const float2*)(ad + 8) : make_float2(0.f, 0.f);
            xq[a][0] = pk2(v0.x, v0.y);
            xq[a][1] = pk2(v0.z, v0.w);
            xq[a][2] = pk2(v1.x, v1.y);
            xq[a][3] = pk2(v1.z, v1.w);
            xq[a][4] = pk2(v2.x, v2.y);
            x20 = fmaf(v0.x, v0.x, fmaf(v0.z, v0.z, fmaf(v1.x, v1.x, fmaf(v1.z, v1.z, x20))));
            x21 = fmaf(v0.y, v0.y, fmaf(v0.w, v0.w, fmaf(v1.y, v1.y, fmaf(v1.w, v1.w, x21))));
            x22 = fmaf(v0.z, v0.z, fmaf(v1.x, v1.x, fmaf(v1.z, v1.z, fmaf(v2.x, v2.x, x22))));
            x23 = fmaf(v0.w, v0.w, fmaf(v1.y, v1.y, fmaf(v1.w, v1.w, fmaf(v2.y, v2.y, x23))));
        }
        ull b01 = pk2(x20, x21);
        ull b23 = pk2(x22, x23);

        #pragma unroll 1
        for (int oL = 0; oL < 2; oL++) {
            int oiL = oL * 4 + i;
            const float* wp  = sw + oiL * 384;
            const float* rpp = &srp[lh][oiL][0];
            const float* cpg = g_cpn + ((size_t)(b * 32 + zo * 8 + oiL) * 24) * NHP + h2b;
            float sc2v = sc2s[oiL];
            float m0 = FLT_MAX, m1 = FLT_MAX, m2 = FLT_MAX, m3 = FLT_MAX;
            #pragma unroll 4
            for (int p = 0; p < 24; p++) {
                ulonglong2 cpq = *(const ulonglong2*)(cpg + p * NHP);
                ull crp2 = dup2(sc2v + rpp[p]);
                ull a01 = add2(add2(b01, crp2), cpq.x);
                ull a23 = add2(add2(b23, crp2), cpq.y);
                const float* wq = wp + p * 16;
                #pragma unroll
                for (int a = 0; a < 4; a++) {
                    #pragma unroll
                    for (int bb = 0; bb < 4; bb++) {
                        ull w2 = dup2(wq[a * 4 + bb]);
                        FMA2(a01, xq[a][bb],     w2);
                        FMA2(a23, xq[a][bb + 1], w2);
                    }
                }
                float d0, d1, d2, d3;
                UNPK(a01, d0, d1); UNPK(a23, d2, d3);
                m0 = fminf(m0, d0); m1 = fminf(m1, d1);
                m2 = fminf(m2, d2); m3 = fminf(m3, d3);
            }
            if (nk) {
                int row = b * 32 + zo * 8 + oiL;
                float* sp = g_sims + (size_t)row * NSUB + h1 * NH + h2b;
                *(float2*)sp = make_float2(m0, m1);
                float tm = fmaxf(m0, m1);
                if (nk == 4) {
                    *(float2*)(sp + 2) = make_float2(m2, m3);
                    tm = fmaxf(tm, fmaxf(m2, m3));
                }
                unsigned uu  = __float_as_uint(tm);
                unsigned key = (uu & 0x80000000u) ? ~uu : (uu | 0x80000000u);
                atomicMax(&smaxu[lh][oiL], key);
            }
        }
    }

    __syncthreads();
    if (t < 32) {
        unsigned uu = smaxu[t >> 3][t & 7];
        smaxf[t >> 3][t & 7] = (uu & 0x80000000u) ? __uint_as_float(uu & 0x7fffffffu)
                                                  : __uint_as_float(~uu);
    }
    __syncthreads();

    // phase 2: in-place exp (thread re-reads only its own writes)
    if (nk) {
        #pragma unroll 1
        for (int oiL = 0; oiL < 8; oiL++) {
            int row = b * 32 + zo * 8 + oiL;
            float mx = smaxf[lh][oiL];
            float* sp = g_sims + (size_t)row * NSUB + h1 * NH + h2b;
            float2 v01 = *(float2*)sp;
            float e0 = __expf(v01.x - mx), e1 = __expf(v01.y - mx);
            *(float2*)sp = make_float2(e0, e1);
            float ssv = e0 + e1;
            if (nk == 4) {
                float2 v23 = *(float2*)(sp + 2);
                float e2 = __expf(v23.x - mx), e3 = __expf(v23.y - mx);
                *(float2*)(sp + 2) = make_float2(e2, e3);
                ssv += e2 + e3;
            }
            atomicAdd(&ssumv[lh][oiL], ssv);
        }
    }
    __syncthreads();
    if (t < 32) {
        int lh2 = t >> 3, oiL = t & 7, h1w = h1base + lh2;
        if (h1w < NH) {
            int row = b * 32 + zo * 8 + oiL;
            g_pmax[row][h1w] = smaxf[lh2][oiL];
            g_psum[row][h1w] = ssumv[lh2][oiL];
        }
    }
}

// ---------------- combine: global max/sum + factor table -------------------
__global__ void combine_kernel() {
    __shared__ float red[256];
    int row = blockIdx.x, tid = threadIdx.x;
    float pm = (tid < NH) ? g_pmax[row][tid] : -FLT_MAX;
    red[tid] = pm; __syncthreads();
    #pragma unroll
    for (int st = 128; st; st >>= 1) {
        if (tid < st) red[tid] = fmaxf(red[tid], red[tid + st]);
        __syncthreads();
    }
    float gmx = red[0];
    __syncthreads();
    float ex = (tid < NH) ? __expf(pm - gmx) : 0.0f;
    red[tid] = (tid < NH) ? g_psum[row][tid] * ex : 0.0f;
    __syncthreads();
    #pragma unroll
    for (int st = 128; st; st >>= 1) {
        if (tid < st) red[tid] += red[tid + st];
        __syncthreads();
    }
    float S = red[0];
    if (tid < NH) g_fac[row][tid] = ex / S;
}

// ---------------- writeout: grid-stride float4 streaming -------------------
__global__ void writeout_kernel(float* __restrict__ out) {
    int row = blockIdx.y;
    const float* fr = g_fac[row];
    const float* sp = g_sims + (size_t)row * NSUB;
    float* op = out + 256 + (size_t)row * NSUB;
    int idx = (blockIdx.x * 1024 + threadIdx.x) * 4;
    if (idx + 4 <= NSUB) {
        float4 e = *(const float4*)(sp + idx);
        int h1a = idx / NH, h1b = (idx + 1) / NH, h1c = (idx + 2) / NH, h1d = (idx + 3) / NH;
        float4 r;
        r.x = (1.0f - e.x * fr[h1a]) * (1.0f / (float)NSUB);
        r.y = (1.0f - e.y * fr[h1b]) * (1.0f / (float)NSUB);
        r.z = (1.0f - e.z * fr[h1c]) * (1.0f / (float)NSUB);
        r.w = (1.0f - e.w * fr[h1d]) * (1.0f / (float)NSUB);
        *(float4*)(op + idx) = r;
    } else {
        for (int j = idx; j < NSUB; j++)
            op[j] = (1.0f - sp[j] * fr[j / NH]) * (1.0f / (float)NSUB);
    }
}

// ---------------- launch ---------------------------------------------------
extern "C" void kernel_launch(void* const* d_in, const int* in_sizes, int n_in,
                              void* d_out, int out_size) {
    const float* graph    = (const float*)d_in[0];
    const float* types    = (const float*)d_in[1];
    const float* features = (const float*)d_in[2];
    const float* ks       = (const float*)d_in[3];
    const float* kr       = (const float*)d_in[4];
    const float* kc       = (const float*)d_in[5];
    float* out = (float*)d_out;

    prep_all_kernel<<<3 + 2 * NH, 256>>>(types, features, ks, kr, kc, out);
    sims_kernel<<<dim3(QG, 2, 4), TPB>>>(graph);
    combine_kernel<<<NROWS, 256>>>();
    writeout_kernel<<<dim3((NSUB + 4095) / 4096, NROWS), 1024>>>(out);
}

// round 16
// speedup vs baseline: 1.2946x; 1.0517x over previous
#include <cuda_runtime.h>
#include <cstdint>
#include <cfloat>

#define NH    218
#define NHP   224        // padded h stride (16B-aligned rows)
#define NSUB  47524      // 218*218
#define NROWS 64         // B * C_OUT * C_IN
#define QG    55         // quad-groups per h1 row (55*4 = 220 >= 218)
#define TPB   220        // 4 h1 rows * 55 quad-groups

typedef unsigned long long ull;

// ---------------- device globals (no allocations allowed) ----------------
__device__ __align__(16) float g_Wn[32 * 24 * 16];          // -2*Kstruct, [oi][p][c]
__device__ float g_c2[32];                                   // ||K||^2+||R||^2+||C||^2
__device__ __align__(16) float g_rpn[2 * 32 * 24 * NHP];     // rpart [b][oi][p][h1]
__device__ __align__(16) float g_cpn[2 * 32 * 24 * NHP];     // cpart [b][oi][p][h2]
__device__ float g_pmax[NROWS][NH];
__device__ float g_psum[NROWS][NH];
__device__ float g_fac[NROWS][NH];
__device__ __align__(16) float g_sims[(size_t)NROWS * NSUB]; // m, then exp(m - blkmax)

__constant__ unsigned char c_P[24][4] = {
  {0,1,2,3},{0,1,3,2},{0,2,1,3},{0,2,3,1},{0,3,1,2},{0,3,2,1},
  {1,0,2,3},{1,0,3,2},{1,2,0,3},{1,2,3,0},{1,3,0,2},{1,3,2,0},
  {2,0,1,3},{2,0,3,1},{2,1,0,3},{2,1,3,0},{2,3,0,1},{2,3,1,0},
  {3,0,1,2},{3,0,2,1},{3,1,0,2},{3,1,2,0},{3,2,0,1},{3,2,1,0}
};

// ---------------- packed f32x2 helpers -----------------------------------
__device__ __forceinline__ ull dup2(float f) {
    ull r;
    asm("mov.b64 %0, {%1, %1};" : "=l"(r) : "f"(f));
    return r;
}
__device__ __forceinline__ ull pk2(float a, float b) {
    ull r;
    asm("mov.b64 %0, {%1, %2};" : "=l"(r) : "f"(a), "f"(b));
    return r;
}
__device__ __forceinline__ ull add2(ull a, ull b) {
    ull r;
    asm("add.rn.f32x2 %0, %1, %2;" : "=l"(r) : "l"(a), "l"(b));
    return r;
}
#define FMA2(acc, x, w) asm("fma.rn.f32x2 %0, %1, %2, %0;" : "+l"(acc) : "l"(x), "l"(w))
#define UNPK(v, lo, hi) asm("mov.b64 {%0, %1}, %2;" : "=f"(lo), "=f"(hi) : "l"(v))

// ---------------- fused prep: weights+c2 / h_mean / rp-cp tables ----------
// bid 0: weights + c2;  bid 1..2: h_mean;  bid 3..66: (b,oi) table rows,
// thread = h  ->  coalesced table stores (stride-1 in h for each p).
__global__ void prep_all_kernel(const float* __restrict__ types,
                                const float* __restrict__ feats,
                                const float* __restrict__ ks,
                                const float* __restrict__ kr,
                                const float* __restrict__ kc,
                                float* __restrict__ out) {
    int bid = blockIdx.x, tid = threadIdx.x;
    if (bid == 0) {
        if (tid < 32) {
            int oi = tid; float s = 0.0f;
            const float* a = ks + oi * 16;
            #pragma unroll
            for (int j = 0; j < 16; j++) s += a[j] * a[j];
            const float* r = kr + oi * 4; const float* c = kc + oi * 4;
            #pragma unroll
            for (int j = 0; j < 4; j++) { s += r[j] * r[j]; s += c[j] * c[j]; }
            g_c2[oi] = s;
        }
        for (int e = tid; e < 32 * 24 * 16; e += blockDim.x) {
            int c = e & 15; int t2 = e >> 4;
            int p = t2 % 24; int oi = t2 / 24;
            int a = c >> 2, bb = c & 3;
            float val = ks[oi * 16 + (int)c_P[p][a] * 4 + (int)c_P[p][bb]];
            g_Wn[(oi * 24 + p) * 16 + c] = -2.0f * val;
        }
    } else if (bid <= 2) {
        int b = bid - 1;
        if (tid < 128) {
            float acc = 0.0f;
            for (int n = 0; n < 224; n++) {
                int lo = (n >= NH) ? ((n - (NH - 2)) >> 1) : 0;
                int hi = min(3, n >> 1);
                acc += (float)(hi - lo + 1) * feats[(b * 224 + n) * 128 + tid];
            }
            out[b * 128 + tid] = acc * (2.0f / (float)NH);
        }
    } else {
        int idx = bid - 3;               // 0..63
        int b = idx >> 5, oi = idx & 31;
        int i = oi & 3;
        int h = tid;
        if (h < NH) {
            const float* tp = types + (b * 4 + i) * 224 + h;
            float t0 = tp[0], t1 = tp[2], t2 = tp[4], t3 = tp[6];
            float t2s = t0 * t0 + t1 * t1 + t2 * t2 + t3 * t3;
            const float* krp = kr + oi * 4;
            const float* kcp = kc + oi * 4;
            #pragma unroll
            for (int p = 0; p < 24; p++) {
                float rd = t0 * krp[c_P[p][0]] + t1 * krp[c_P[p][1]] + t2 * krp[c_P[p][2]] + t3 * krp[c_P[p][3]];
                float cd = t0 * kcp[c_P[p][0]] + t1 * kcp[c_P[p][1]] + t2 * kcp[c_P[p][2]] + t3 * kcp[c_P[p][3]];
                size_t lin = ((size_t)(b * 32 + oi) * 24 + p) * NHP + h;
                g_rpn[lin] = t2s - 2.0f * rd;
                g_cpn[lin] = t2s - 2.0f * cd;
            }
        }
    }
}

// ---------------- sims: R7-exact 4-subs/thread FFMA2 kernel ----------------
// thread = (lh in 0..3, quad-group u in 0..54): subs h2 = 4u..4u+3
// h1 = 4*blockIdx.x + lh; h1 masking required (tiles span 220 > 218).
__global__ void __launch_bounds__(TPB, 3)
sims_kernel(const float* __restrict__ graph) {
    __shared__ __align__(16) float sw[8 * 24 * 16];   // 12 KB: [oiL][p][c]
    __shared__ float    srp[4][8][24];                // rpart for 4 h1
    __shared__ float    sc2s[8];
    __shared__ unsigned smaxu[4][8];
    __shared__ float    smaxf[4][8];
    __shared__ float    ssumv[4][8];

    int t  = threadIdx.x;
    int b  = blockIdx.y;
    int zo = blockIdx.z;              // o-pair index: o = zo*2 + oL
    int h1base = blockIdx.x * 4;

    {
        const float4* srcw = (const float4*)(g_Wn + zo * 8 * 384);
        float4* dstw = (float4*)sw;
        for (int e = t; e < 768; e += TPB) dstw[e] = srcw[e];
        for (int e = t; e < 768; e += TPB) {
            int lh = e / 192, r = e % 192, oiL = r / 24, p = r % 24;
            int h1s = min(h1base + lh, NH - 1);
            srp[lh][oiL][p] = g_rpn[((size_t)(b * 32 + zo * 8 + oiL) * 24 + p) * NHP + h1s];
        }
        if (t < 8) sc2s[t] = g_c2[zo * 8 + t];
        if (t < 32) { smaxu[t >> 3][t & 7] = 0u; ssumv[t >> 3][t & 7] = 0.0f; }
    }
    __syncthreads();

    int lh = t / QG, u = t - lh * QG;
    int h1 = h1base + lh;
    bool h1v = h1 < NH;
    int h1c = h1v ? h1 : NH - 1;
    int h2b = 4 * u;
    int nk = h1v ? ((h2b + 4 <= NH) ? 4 : NH - h2b) : 0;  // 4, 2 (u=54), or 0
    bool fullq = (u < QG - 1);

    #pragma unroll 1
    for (int i = 0; i < 4; i++) {
        ull xq[4][5];
        float x20 = 0.f, x21 = 0.f, x22 = 0.f, x23 = 0.f;
        const float* gp = graph + (((size_t)(b * 4 + i) * 224) + h1c) * 224 + h2b;
        #pragma unroll
        for (int a = 0; a < 4; a++) {
            const float* ad = gp + (2 * a) * 224;
            float4 v0 = *(const float4*)ad;          // g0..g3
            float4 v1 = *(const float4*)(ad + 4);    // g4..g7
            float2 v2 = fullq ? *(const float2*)(ad + 8) : make_float2(0.f, 0.f);
            xq[a][0] = pk2(v0.x, v0.y);
            xq[a][1] = pk2(v0.z, v0.w);
            xq[a][2] = pk2(v1.x, v1.y);
            xq[a][3] = pk2(v1.z, v1.w);
            xq[a][4] = pk2(v2.x, v2.y);
            x20 = fmaf(v0.x, v0.x, fmaf(v0.z, v0.z, fmaf(v1.x, v1.x, fmaf(v1.z, v1.z, x20))));
            x21 = fmaf(v0.y, v0.y, fmaf(v0.w, v0.w, fmaf(v1.y, v1.y, fmaf(v1.w, v1.w, x21))));
            x22 = fmaf(v0.z, v0.z, fmaf(v1.x, v1.x, fmaf(v1.z, v1.z, fmaf(v2.x, v2.x, x22))));
            x23 = fmaf(v0.w, v0.w, fmaf(v1.y, v1.y, fmaf(v1.w, v1.w, fmaf(v2.y, v2.y, x23))));
        }
        ull b01 = pk2(x20, x21);
        ull b23 = pk2(x22, x23);

        #pragma unroll 1
        for (int oL = 0; oL < 2; oL++) {
            int oiL = oL * 4 + i;
            const float* wp  = sw + oiL * 384;
            const float* rpp = &srp[lh][oiL][0];
            const float* cpg = g_cpn + ((size_t)(b * 32 + zo * 8 + oiL) * 24) * NHP + h2b;
            float sc2v = sc2s[oiL];
            float m0 = FLT_MAX, m1 = FLT_MAX, m2 = FLT_MAX, m3 = FLT_MAX;
            #pragma unroll 4
            for (int p = 0; p < 24; p++) {
                ulonglong2 cpq = *(const ulonglong2*)(cpg + p * NHP);
                ull crp2 = dup2(sc2v + rpp[p]);
                ull a01 = add2(add2(b01, crp2), cpq.x);
                ull a23 = add2(add2(b23, crp2), cpq.y);
                const float* wq = wp + p * 16;
                #pragma unroll
                for (int a = 0; a < 4; a++) {
                    #pragma unroll
                    for (int bb = 0; bb < 4; bb++) {
                        ull w2 = dup2(wq[a * 4 + bb]);
                        FMA2(a01, xq[a][bb],     w2);
                        FMA2(a23, xq[a][bb + 1], w2);
                    }
                }
                float d0, d1, d2, d3;
                UNPK(a01, d0, d1); UNPK(a23, d2, d3);
                m0 = fminf(m0, d0); m1 = fminf(m1, d1);
                m2 = fminf(m2, d2); m3 = fminf(m3, d3);
            }
            if (nk) {
                int row = b * 32 + zo * 8 + oiL;
                float* sp = g_sims + (size_t)row * NSUB + h1 * NH + h2b;
                *(float2*)sp = make_float2(m0, m1);
                float tm = fmaxf(m0, m1);
                if (nk == 4) {
                    *(float2*)(sp + 2) = make_float2(m2, m3);
                    tm = fmaxf(tm, fmaxf(m2, m3));
                }
                unsigned uu  = __float_as_uint(tm);
                unsigned key = (uu & 0x80000000u) ? ~uu : (uu | 0x80000000u);
                atomicMax(&smaxu[lh][oiL], key);
            }
        }
    }

    __syncthreads();
    if (t < 32) {
        unsigned uu = smaxu[t >> 3][t & 7];
        smaxf[t >> 3][t & 7] = (uu & 0x80000000u) ? __uint_as_float(uu & 0x7fffffffu)
                                                  : __uint_as_float(~uu);
    }
    __syncthreads();

    // phase 2: in-place exp (thread re-reads only its own writes)
    if (nk) {
        #pragma unroll 1
        for (int oiL = 0; oiL < 8; oiL++) {
            int row = b * 32 + zo * 8 + oiL;
            float mx = smaxf[lh][oiL];
            float* sp = g_sims + (size_t)row * NSUB + h1 * NH + h2b;
            float2 v01 = *(float2*)sp;
            float e0 = __expf(v01.x - mx), e1 = __expf(v01.y - mx);
            *(float2*)sp = make_float2(e0, e1);
            float ssv = e0 + e1;
            if (nk == 4) {
                float2 v23 = *(float2*)(sp + 2);
                float e2 = __expf(v23.x - mx), e3 = __expf(v23.y - mx);
                *(float2*)(sp + 2) = make_float2(e2, e3);
                ssv += e2 + e3;
            }
            atomicAdd(&ssumv[lh][oiL], ssv);
        }
    }
    __syncthreads();
    if (t < 32) {
        int lh2 = t >> 3, oiL = t & 7, h1w = h1base + lh2;
        if (h1w < NH) {
            int row = b * 32 + zo * 8 + oiL;
            g_pmax[row][h1w] = smaxf[lh2][oiL];
            g_psum[row][h1w] = ssumv[lh2][oiL];
        }
    }
}

// ---------------- combine: global max/sum + factor table -------------------
__global__ void combine_kernel() {
    __shared__ float red[256];
    int row = blockIdx.x, tid = threadIdx.x;
    float pm = (tid < NH) ? g_pmax[row][tid] : -FLT_MAX;
    red[tid] = pm; __syncthreads();
    #pragma unroll
    for (int st = 128; st; st >>= 1) {
        if (tid < st) red[tid] = fmaxf(red[tid], red[tid + st]);
        __syncthreads();
    }
    float gmx = red[0];
    __syncthreads();
    float ex = (tid < NH) ? __expf(pm - gmx) : 0.0f;
    red[tid] = (tid < NH) ? g_psum[row][tid] * ex : 0.0f;
    __syncthreads();
    #pragma unroll
    for (int st = 128; st; st >>= 1) {
        if (tid < st) red[tid] += red[tid + st];
        __syncthreads();
    }
    float S = red[0];
    if (tid < NH) g_fac[row][tid] = ex / S;
}

// ---------------- writeout: 4 independent float4 chunks per thread ---------
// NSUB % 4 == 0, so float4 chunks never straddle the row end.
__global__ void writeout_kernel(float* __restrict__ out) {
    int row = blockIdx.y;
    const float* fr = g_fac[row];
    const float* sp = g_sims + (size_t)row * NSUB;
    float* op = out + 256 + (size_t)row * NSUB;
    int base = blockIdx.x * 1024 + threadIdx.x;     // 256 threads, 4 chunks each
    #pragma unroll
    for (int j = 0; j < 4; j++) {
        int idx = (base + j * 256) * 4;
        if (idx < NSUB) {
            float4 e = *(const float4*)(sp + idx);
            int h1a = idx / NH, h1b = (idx + 1) / NH, h1c = (idx + 2) / NH, h1d = (idx + 3) / NH;
            float4 r;
            r.x = (1.0f - e.x * fr[h1a]) * (1.0f / (float)NSUB);
            r.y = (1.0f - e.y * fr[h1b]) * (1.0f / (float)NSUB);
            r.z = (1.0f - e.z * fr[h1c]) * (1.0f / (float)NSUB);
            r.w = (1.0f - e.w * fr[h1d]) * (1.0f / (float)NSUB);
            *(float4*)(op + idx) = r;
        }
    }
}

// ---------------- launch ---------------------------------------------------
extern "C" void kernel_launch(void* const* d_in, const int* in_sizes, int n_in,
                              void* d_out, int out_size) {
    const float* graph    = (const float*)d_in[0];
    const float* types    = (const float*)d_in[1];
    const float* features = (const float*)d_in[2];
    const float* ks       = (const float*)d_in[3];
    const float* kr       = (const float*)d_in[4];
    const float* kc       = (const float*)d_in[5];
    float* out = (float*)d_out;

    prep_all_kernel<<<3 + NROWS, 256>>>(types, features, ks, kr, kc, out);
    sims_kernel<<<dim3(QG, 2, 4), TPB>>>(graph);
    combine_kernel<<<NROWS, 256>>>();
    writeout_kernel<<<dim3((NSUB / 4 + 1023) / 1024, NROWS), 256>>>(out);
}

// round 17
// speedup vs baseline: 1.4313x; 1.1056x over previous
#include <cuda_runtime.h>
#include <cstdint>
#include <cfloat>

#define NH    218
#define NHP   224        // padded h stride (16B-aligned rows)
#define NSUB  47524      // 218*218
#define NROWS 64         // B * C_OUT * C_IN
#define QG    55         // quad-groups per h1 row (55*4 = 220 >= 218)
#define TPB   220        // 4 h1 rows * 55 quad-groups

typedef unsigned long long ull;

// ---------------- device globals (no allocations allowed) ----------------
__device__ __align__(16) float g_Wn[32 * 24 * 16];          // -2*Kstruct, [oi][p][c]
__device__ float g_c2[32];                                   // ||K||^2+||R||^2+||C||^2
__device__ __align__(16) float g_rpn[2 * 32 * 24 * NHP];     // rpart [b][oi][p][h1]
__device__ __align__(16) float g_cpn[2 * 32 * 24 * NHP];     // cpart [b][oi][p][h2]
__device__ float g_pmax[NROWS][NH];
__device__ float g_psum[NROWS][NH];
__device__ __align__(16) float g_sims[(size_t)NROWS * NSUB]; // exp(m - blkmax)

__constant__ unsigned char c_P[24][4] = {
  {0,1,2,3},{0,1,3,2},{0,2,1,3},{0,2,3,1},{0,3,1,2},{0,3,2,1},
  {1,0,2,3},{1,0,3,2},{1,2,0,3},{1,2,3,0},{1,3,0,2},{1,3,2,0},
  {2,0,1,3},{2,0,3,1},{2,1,0,3},{2,1,3,0},{2,3,0,1},{2,3,1,0},
  {3,0,1,2},{3,0,2,1},{3,1,0,2},{3,1,2,0},{3,2,0,1},{3,2,1,0}
};

// ---------------- packed f32x2 helpers -----------------------------------
__device__ __forceinline__ ull dup2(float f) {
    ull r;
    asm("mov.b64 %0, {%1, %1};" : "=l"(r) : "f"(f));
    return r;
}
__device__ __forceinline__ ull pk2(float a, float b) {
    ull r;
    asm("mov.b64 %0, {%1, %2};" : "=l"(r) : "f"(a), "f"(b));
    return r;
}
__device__ __forceinline__ ull add2(ull a, ull b) {
    ull r;
    asm("add.rn.f32x2 %0, %1, %2;" : "=l"(r) : "l"(a), "l"(b));
    return r;
}
#define FMA2(acc, x, w) asm("fma.rn.f32x2 %0, %1, %2, %0;" : "+l"(acc) : "l"(x), "l"(w))
#define UNPK(v, lo, hi) asm("mov.b64 {%0, %1}, %2;" : "=f"(lo), "=f"(hi) : "l"(v))

// ---------------- fused prep: weights+c2 / h_mean / rp-cp tables ----------
__global__ void prep_all_kernel(const float* __restrict__ types,
                                const float* __restrict__ feats,
                                const float* __restrict__ ks,
                                const float* __restrict__ kr,
                                const float* __restrict__ kc,
                                float* __restrict__ out) {
    int bid = blockIdx.x, tid = threadIdx.x;
    if (bid == 0) {
        if (tid < 32) {
            int oi = tid; float s = 0.0f;
            const float* a = ks + oi * 16;
            #pragma unroll
            for (int j = 0; j < 16; j++) s += a[j] * a[j];
            const float* r = kr + oi * 4; const float* c = kc + oi * 4;
            #pragma unroll
            for (int j = 0; j < 4; j++) { s += r[j] * r[j]; s += c[j] * c[j]; }
            g_c2[oi] = s;
        }
        for (int e = tid; e < 32 * 24 * 16; e += blockDim.x) {
            int c = e & 15; int t2 = e >> 4;
            int p = t2 % 24; int oi = t2 / 24;
            int a = c >> 2, bb = c & 3;
            float val = ks[oi * 16 + (int)c_P[p][a] * 4 + (int)c_P[p][bb]];
            g_Wn[(oi * 24 + p) * 16 + c] = -2.0f * val;
        }
    } else if (bid <= 2) {
        int b = bid - 1;
        if (tid < 128) {
            float acc = 0.0f;
            for (int n = 0; n < 224; n++) {
                int lo = (n >= NH) ? ((n - (NH - 2)) >> 1) : 0;
                int hi = min(3, n >> 1);
                acc += (float)(hi - lo + 1) * feats[(b * 224 + n) * 128 + tid];
            }
            out[b * 128 + tid] = acc * (2.0f / (float)NH);
        }
    } else {
        int idx = bid - 3;               // 0..63, block = (b, oi); thread = h
        int b = idx >> 5, oi = idx & 31;
        int i = oi & 3;
        int h = tid;
        if (h < NH) {
            const float* tp = types + (b * 4 + i) * 224 + h;
            float t0 = tp[0], t1 = tp[2], t2 = tp[4], t3 = tp[6];
            float t2s = t0 * t0 + t1 * t1 + t2 * t2 + t3 * t3;
            const float* krp = kr + oi * 4;
            const float* kcp = kc + oi * 4;
            #pragma unroll
            for (int p = 0; p < 24; p++) {
                float rd = t0 * krp[c_P[p][0]] + t1 * krp[c_P[p][1]] + t2 * krp[c_P[p][2]] + t3 * krp[c_P[p][3]];
                float cd = t0 * kcp[c_P[p][0]] + t1 * kcp[c_P[p][1]] + t2 * kcp[c_P[p][2]] + t3 * kcp[c_P[p][3]];
                size_t lin = ((size_t)(b * 32 + oi) * 24 + p) * NHP + h;
                g_rpn[lin] = t2s - 2.0f * rd;
                g_cpn[lin] = t2s - 2.0f * cd;
            }
        }
    }
}

// ---------------- sims: o-split, 4 subs/thread, occupancy 4 ----------------
// block = (h1 tile, b, o); handles 4 (i) channels for ONE o.
// thread = (lh in 0..3, quad-group u in 0..54): subs h2 = 4u..4u+3.
__global__ void __launch_bounds__(TPB, 4)
sims_kernel(const float* __restrict__ graph) {
    __shared__ __align__(16) float sw[4 * 24 * 16];   // 6 KB: [iL][p][c] for this o
    __shared__ float    srp[4][4][24];                // rpart for 4 h1 x 4 i
    __shared__ float    sc2s[4];
    __shared__ unsigned smaxu[4][4];
    __shared__ float    smaxf[4][4];
    __shared__ float    ssumv[4][4];

    int t  = threadIdx.x;
    int b  = blockIdx.y;
    int o  = blockIdx.z;              // 0..7
    int h1base = blockIdx.x * 4;

    {
        const float4* srcw = (const float4*)(g_Wn + o * 4 * 384);
        float4* dstw = (float4*)sw;
        for (int e = t; e < 384; e += TPB) dstw[e] = srcw[e];
        for (int e = t; e < 384; e += TPB) {
            int lh = e / 96, r = e % 96, iL = r / 24, p = r % 24;
            int h1s = min(h1base + lh, NH - 1);
            srp[lh][iL][p] = g_rpn[((size_t)(b * 32 + o * 4 + iL) * 24 + p) * NHP + h1s];
        }
        if (t < 4) sc2s[t] = g_c2[o * 4 + t];
        if (t < 16) { smaxu[t >> 2][t & 3] = 0u; ssumv[t >> 2][t & 3] = 0.0f; }
    }
    __syncthreads();

    int lh = t / QG, u = t - lh * QG;
    int h1 = h1base + lh;
    bool h1v = h1 < NH;
    int h1c = h1v ? h1 : NH - 1;
    int h2b = 4 * u;
    int nk = h1v ? ((h2b + 4 <= NH) ? 4 : NH - h2b) : 0;  // 4, 2 (u=54), or 0
    bool fullq = (u < QG - 1);

    #pragma unroll 1
    for (int i = 0; i < 4; i++) {
        ull xq[4][5];
        float x20 = 0.f, x21 = 0.f, x22 = 0.f, x23 = 0.f;
        const float* gp = graph + (((size_t)(b * 4 + i) * 224) + h1c) * 224 + h2b;
        #pragma unroll
        for (int a = 0; a < 4; a++) {
            const float* ad = gp + (2 * a) * 224;
            float4 v0 = *(const float4*)ad;          // g0..g3
            float4 v1 = *(const float4*)(ad + 4);    // g4..g7
            float2 v2 = fullq ? *(const float2*)(ad + 8) : make_float2(0.f, 0.f);
            xq[a][0] = pk2(v0.x, v0.y);
            xq[a][1] = pk2(v0.z, v0.w);
            xq[a][2] = pk2(v1.x, v1.y);
            xq[a][3] = pk2(v1.z, v1.w);
            xq[a][4] = pk2(v2.x, v2.y);
            x20 = fmaf(v0.x, v0.x, fmaf(v0.z, v0.z, fmaf(v1.x, v1.x, fmaf(v1.z, v1.z, x20))));
            x21 = fmaf(v0.y, v0.y, fmaf(v0.w, v0.w, fmaf(v1.y, v1.y, fmaf(v1.w, v1.w, x21))));
            x22 = fmaf(v0.z, v0.z, fmaf(v1.x, v1.x, fmaf(v1.z, v1.z, fmaf(v2.x, v2.x, x22))));
            x23 = fmaf(v0.w, v0.w, fmaf(v1.y, v1.y, fmaf(v1.w, v1.w, fmaf(v2.y, v2.y, x23))));
        }
        ull b01 = pk2(x20, x21);
        ull b23 = pk2(x22, x23);

        {
            const float* wp  = sw + i * 384;
            const float* rpp = &srp[lh][i][0];
            const float* cpg = g_cpn + ((size_t)(b * 32 + o * 4 + i) * 24) * NHP + h2b;
            float sc2v = sc2s[i];
            float m0 = FLT_MAX, m1 = FLT_MAX, m2 = FLT_MAX, m3 = FLT_MAX;
            #pragma unroll 2
            for (int p = 0; p < 24; p++) {
                ulonglong2 cpq = *(const ulonglong2*)(cpg + p * NHP);
                ull crp2 = dup2(sc2v + rpp[p]);
                ull a01 = add2(add2(b01, crp2), cpq.x);
                ull a23 = add2(add2(b23, crp2), cpq.y);
                const float* wq = wp + p * 16;
                #pragma unroll
                for (int a = 0; a < 4; a++) {
                    #pragma unroll
                    for (int bb = 0; bb < 4; bb++) {
                        ull w2 = dup2(wq[a * 4 + bb]);
                        FMA2(a01, xq[a][bb],     w2);
                        FMA2(a23, xq[a][bb + 1], w2);
                    }
                }
                float d0, d1, d2, d3;
                UNPK(a01, d0, d1); UNPK(a23, d2, d3);
                m0 = fminf(m0, d0); m1 = fminf(m1, d1);
                m2 = fminf(m2, d2); m3 = fminf(m3, d3);
            }
            if (nk) {
                int row = b * 32 + o * 4 + i;
                float* sp = g_sims + (size_t)row * NSUB + h1 * NH + h2b;
                *(float2*)sp = make_float2(m0, m1);
                float tm = fmaxf(m0, m1);
                if (nk == 4) {
                    *(float2*)(sp + 2) = make_float2(m2, m3);
                    tm = fmaxf(tm, fmaxf(m2, m3));
                }
                unsigned uu  = __float_as_uint(tm);
                unsigned key = (uu & 0x80000000u) ? ~uu : (uu | 0x80000000u);
                atomicMax(&smaxu[lh][i], key);
            }
        }
    }

    __syncthreads();
    if (t < 16) {
        unsigned uu = smaxu[t >> 2][t & 3];
        smaxf[t >> 2][t & 3] = (uu & 0x80000000u) ? __uint_as_float(uu & 0x7fffffffu)
                                                  : __uint_as_float(~uu);
    }
    __syncthreads();

    // phase 2: in-place exp (thread re-reads only its own writes)
    if (nk) {
        #pragma unroll 1
        for (int iL = 0; iL < 4; iL++) {
            int row = b * 32 + o * 4 + iL;
            float mx = smaxf[lh][iL];
            float* sp = g_sims + (size_t)row * NSUB + h1 * NH + h2b;
            float2 v01 = *(float2*)sp;
            float e0 = __expf(v01.x - mx), e1 = __expf(v01.y - mx);
            *(float2*)sp = make_float2(e0, e1);
            float ssv = e0 + e1;
            if (nk == 4) {
                float2 v23 = *(float2*)(sp + 2);
                float e2 = __expf(v23.x - mx), e3 = __expf(v23.y - mx);
                *(float2*)(sp + 2) = make_float2(e2, e3);
                ssv += e2 + e3;
            }
            atomicAdd(&ssumv[lh][iL], ssv);
        }
    }
    __syncthreads();
    if (t < 16) {
        int lh2 = t >> 2, iL = t & 3, h1w = h1base + lh2;
        if (h1w < NH) {
            int row = b * 32 + o * 4 + iL;
            g_pmax[row][h1w] = smaxf[lh2][iL];
            g_psum[row][h1w] = ssumv[lh2][iL];
        }
    }
}

// ---------------- writeout: fused combine + streaming ----------------------
// Each block redundantly reduces its row's 218 (pmax, psum) -> fac in smem,
// then streams its 4096-element chunk. NSUB % 4 == 0.
__global__ void writeout_kernel(float* __restrict__ out) {
    __shared__ float red[256];
    __shared__ float sfac[NH];
    int row = blockIdx.y, t = threadIdx.x;

    float pm = (t < NH) ? g_pmax[row][t] : -FLT_MAX;
    red[t] = pm; __syncthreads();
    #pragma unroll
    for (int st = 128; st; st >>= 1) {
        if (t < st) red[t] = fmaxf(red[t], red[t + st]);
        __syncthreads();
    }
    float gmx = red[0];
    __syncthreads();
    float ex = (t < NH) ? __expf(pm - gmx) : 0.0f;
    red[t] = (t < NH) ? g_psum[row][t] * ex : 0.0f;
    __syncthreads();
    #pragma unroll
    for (int st = 128; st; st >>= 1) {
        if (t < st) red[t] += red[t + st];
        __syncthreads();
    }
    float S = red[0];
    if (t < NH) sfac[t] = ex / S;
    __syncthreads();

    const float* sp = g_sims + (size_t)row * NSUB;
    float* op = out + 256 + (size_t)row * NSUB;
    int base = blockIdx.x * 1024 + t;               // 256 threads, 4 chunks each
    #pragma unroll
    for (int j = 0; j < 4; j++) {
        int idx = (base + j * 256) * 4;
        if (idx < NSUB) {
            float4 e = *(const float4*)(sp + idx);
            int h1a = idx / NH, h1b = (idx + 1) / NH, h1c = (idx + 2) / NH, h1d = (idx + 3) / NH;
            float4 r;
            r.x = (1.0f - e.x * sfac[h1a]) * (1.0f / (float)NSUB);
            r.y = (1.0f - e.y * sfac[h1b]) * (1.0f / (float)NSUB);
            r.z = (1.0f - e.z * sfac[h1c]) * (1.0f / (float)NSUB);
            r.w = (1.0f - e.w * sfac[h1d]) * (1.0f / (float)NSUB);
            *(float4*)(op + idx) = r;
        }
    }
}

// ---------------- launch ---------------------------------------------------
extern "C" void kernel_launch(void* const* d_in, const int* in_sizes, int n_in,
                              void* d_out, int out_size) {
    const float* graph    = (const float*)d_in[0];
    const float* types    = (const float*)d_in[1];
    const float* features = (const float*)d_in[2];
    const float* ks       = (const float*)d_in[3];
    const float* kr       = (const float*)d_in[4];
    const float* kc       = (const float*)d_in[5];
    float* out = (float*)d_out;

    prep_all_kernel<<<3 + NROWS, 256>>>(types, features, ks, kr, kc, out);
    sims_kernel<<<dim3(QG, 2, 8), TPB>>>(graph);
    writeout_kernel<<<dim3((NSUB / 4 + 1023) / 1024, NROWS), 256>>>(out);
}